// round 3
// baseline (speedup 1.0000x reference)
#include <cuda_runtime.h>
#include <cstdint>

// ---------------- problem constants ----------------
#define NN 65536
#define DD 1024
#define KM 64
#define NSTAGE 64          // DD / 16
typedef unsigned long long ull;

// ---------------- device state ----------------
__device__ float  g_x2[NN];
__device__ float  g_dmin[NN];
__device__ int    g_ztmp[NN];
__device__ int    g_z[NN];
__device__ float  g_m2[KM];
__device__ float  g_nc[DD];
__device__ float  g_colpart[64][DD];
__device__ float  g_farpart[128][DD];
__device__ float  g_objpart[8192];
__device__ float  g_sumpart[8][64][KM][128];   // [dchunk][pblk][k][dsub] ~16.8 MB
__device__ int    g_counts[KM];
__device__ int    g_farcnt;
__device__ int    g_K, g_Knew, g_create, g_done, g_it;
__device__ double g_prev;

// ---------------- helpers ----------------
__device__ __forceinline__ ull pk2(float a, float b) {
    ull r; asm("mov.b64 %0, {%1,%2};" : "=l"(r) : "f"(a), "f"(b)); return r;
}
__device__ __forceinline__ void fma2(ull &acc, ull a, ull b) {
    asm("fma.rn.f32x2 %0, %1, %2, %0;" : "+l"(acc) : "l"(a), "l"(b));
}
__device__ __forceinline__ void un2(ull v, float &x, float &y) {
    asm("mov.b64 {%0,%1}, %2;" : "=f"(x), "=f"(y) : "l"(v));
}

// ---------------- init kernels ----------------
// I1: per-point squared norm (warp per point)
__global__ void kI1(const float* __restrict__ X) {
    int tid = threadIdx.x, w = tid >> 5, lane = tid & 31;
    int i = blockIdx.x * 8 + w;
    const float* row = X + (size_t)i * DD;
    float s = 0.f;
#pragma unroll
    for (int j = 0; j < 32; j++) { float v = row[lane + 32 * j]; s = fmaf(v, v, s); }
#pragma unroll
    for (int off = 16; off > 0; off >>= 1) s += __shfl_xor_sync(0xFFFFFFFFu, s, off);
    if (lane == 0) g_x2[i] = s;
}

// I2: column-sum partials for the initial mean
__global__ void kI2(const float* __restrict__ X) {
    int tid = threadIdx.x;
    float a0 = 0.f, a1 = 0.f, a2 = 0.f, a3 = 0.f;
    int base = blockIdx.x * 1024;
    for (int p = 0; p < 1024; p++) {
        const float* row = X + (size_t)(base + p) * DD;
        a0 += row[tid]; a1 += row[tid + 256]; a2 += row[tid + 512]; a3 += row[tid + 768];
    }
    g_colpart[blockIdx.x][tid]       = a0;
    g_colpart[blockIdx.x][tid + 256] = a1;
    g_colpart[blockIdx.x][tid + 512] = a2;
    g_colpart[blockIdx.x][tid + 768] = a3;
}

// I3: finalize mu0, zero other slots, m2, reset scalars
__global__ void kI3(float* __restrict__ mu) {
    __shared__ float sm[1024];
    int tid = threadIdx.x;
    float s = 0.f;
    for (int b = 0; b < 64; b++) s += g_colpart[b][tid];
    float m = s * (1.0f / 65536.0f);
    mu[tid] = m;
    for (int k = 1; k < KM; k++) mu[(size_t)k * DD + tid] = 0.f;
    sm[tid] = m * m;
    __syncthreads();
    for (int off = 512; off > 0; off >>= 1) { if (tid < off) sm[tid] += sm[tid + off]; __syncthreads(); }
    if (tid == 0) g_m2[0] = sm[0];
    if (tid >= 1 && tid < KM) g_m2[tid] = 0.f;
    if (tid == 0) { g_K = 1; g_done = 0; g_it = 0; g_prev = 0.0; g_create = 0; g_farcnt = 0; }
}

// ---------------- A: fused GEMM + masked min/argmin ----------------
// 512 blocks x 128 threads; block tile 128 points x 64 clusters; thread tile 8x8 via f32x2.
__global__ __launch_bounds__(128) void kA(const float* __restrict__ X, const float* __restrict__ mu) {
    if (g_done) return;
    if (blockIdx.x == 0 && threadIdx.x == 0) g_farcnt = 0;
    __shared__ float sX[16][128];
    __shared__ float sB[16][64];
    __shared__ float sx2[128];
    __shared__ float sm2[64];
    const int tid = threadIdx.x;
    const int tx = tid & 7, ty = tid >> 3;
    const int pbase = blockIdx.x * 128;
    sx2[tid] = g_x2[pbase + tid];
    if (tid < 64) sm2[tid] = g_m2[tid];
    const int K = g_K;

    ull acc[8][4];
#pragma unroll
    for (int p = 0; p < 8; p++)
#pragma unroll
        for (int q = 0; q < 4; q++) acc[p][q] = 0ull;

    for (int stage = 0; stage < NSTAGE; ++stage) {
        const int dbase = stage * 16;
        __syncthreads();
#pragma unroll
        for (int it = 0; it < 4; ++it) {
            int f = tid + it * 128;
            int p = f >> 2, q = f & 3;
            float4 v = *reinterpret_cast<const float4*>(&X[(size_t)(pbase + p) * DD + dbase + q * 4]);
            sX[q * 4 + 0][p] = v.x; sX[q * 4 + 1][p] = v.y;
            sX[q * 4 + 2][p] = v.z; sX[q * 4 + 3][p] = v.w;
        }
#pragma unroll
        for (int it = 0; it < 2; ++it) {
            int f = tid + it * 128;
            int k = f >> 2, q = f & 3;
            float4 v = *reinterpret_cast<const float4*>(&mu[(size_t)k * DD + dbase + q * 4]);
            sB[q * 4 + 0][k] = v.x; sB[q * 4 + 1][k] = v.y;
            sB[q * 4 + 2][k] = v.z; sB[q * 4 + 3][k] = v.w;
        }
        __syncthreads();
#pragma unroll
        for (int dd = 0; dd < 16; ++dd) {
            float4 a0 = *reinterpret_cast<const float4*>(&sX[dd][ty * 8]);
            float4 a1 = *reinterpret_cast<const float4*>(&sX[dd][ty * 8 + 4]);
            float4 b0 = *reinterpret_cast<const float4*>(&sB[dd][tx * 8]);
            float4 b1 = *reinterpret_cast<const float4*>(&sB[dd][tx * 8 + 4]);
            ull bp0 = pk2(b0.x, b0.y), bp1 = pk2(b0.z, b0.w);
            ull bp2 = pk2(b1.x, b1.y), bp3 = pk2(b1.z, b1.w);
            float av[8] = {a0.x, a0.y, a0.z, a0.w, a1.x, a1.y, a1.z, a1.w};
#pragma unroll
            for (int p = 0; p < 8; p++) {
                ull xx = pk2(av[p], av[p]);
                fma2(acc[p][0], xx, bp0);
                fma2(acc[p][1], xx, bp1);
                fma2(acc[p][2], xx, bp2);
                fma2(acc[p][3], xx, bp3);
            }
        }
    }

    // epilogue: dist = (x2 - 2S) + m2, mask k>=K, min + first-index argmin
#pragma unroll
    for (int p = 0; p < 8; p++) {
        int prow = ty * 8 + p;
        float x2v = sx2[prow];
        float best = 3.0e38f; int bidx = 0;
#pragma unroll
        for (int q = 0; q < 4; q++) {
            float s0, s1; un2(acc[p][q], s0, s1);
            int k0 = tx * 8 + q * 2;
            float d0 = fmaf(-2.f, s0, x2v) + sm2[k0];
            float d1 = fmaf(-2.f, s1, x2v) + sm2[k0 + 1];
            if (k0 < K && d0 < best) { best = d0; bidx = k0; }
            if (k0 + 1 < K && d1 < best) { best = d1; bidx = k0 + 1; }
        }
#pragma unroll
        for (int off = 1; off < 8; off <<= 1) {
            float ov = __shfl_xor_sync(0xFFFFFFFFu, best, off);
            int   oi = __shfl_xor_sync(0xFFFFFFFFu, bidx, off);
            if (ov < best || (ov == best && oi < bidx)) { best = ov; bidx = oi; }
        }
        if (tx == 0) { g_dmin[pbase + prow] = best; g_ztmp[pbase + prow] = bidx; }
    }
}

// ---------------- B1: masked sum of far points (partials) ----------------
__global__ void kB1(const float* __restrict__ X) {
    if (g_done) return;
    int tid = threadIdx.x;
    float a0 = 0.f, a1 = 0.f, a2 = 0.f, a3 = 0.f;
    int base = blockIdx.x * 512;
    int cnt = 0;
    for (int p = 0; p < 512; p++) {
        int i = base + p;
        if (g_dmin[i] > 1000.0f) {
            const float* row = X + (size_t)i * DD;
            a0 += row[tid]; a1 += row[tid + 256]; a2 += row[tid + 512]; a3 += row[tid + 768];
            cnt++;
        }
    }
    g_farpart[blockIdx.x][tid]       = a0;
    g_farpart[blockIdx.x][tid + 256] = a1;
    g_farpart[blockIdx.x][tid + 512] = a2;
    g_farpart[blockIdx.x][tid + 768] = a3;
    if (tid == 0) atomicAdd(&g_farcnt, cnt);
}

// ---------------- B2: new center, create flag, reset counts ----------------
__global__ void kB2() {
    if (g_done) return;
    int tid = threadIdx.x;       // 1024
    float s = 0.f;
    for (int b = 0; b < 128; b++) s += g_farpart[b][tid];
    int cnt = g_farcnt;
    g_nc[tid] = s / fmaxf((float)cnt, 1.0f);
    if (tid < KM) g_counts[tid] = 0;
    if (tid == 0) {
        int K = g_K;
        int create = (cnt > 0 && K < KM) ? 1 : 0;
        g_create = create;
        g_Knew = K + create;
    }
}

// ---------------- C1: finalize z/dvals, counts, obj partials ----------------
__global__ void kC1(const float* __restrict__ X) {
    if (g_done) return;
    __shared__ int sh[KM];
    __shared__ float wv[8];
    int tid = threadIdx.x, w = tid >> 5, lane = tid & 31;
    if (tid < KM) sh[tid] = 0;
    __syncthreads();
    int i = blockIdx.x * 8 + w;
    int create = g_create;
    int K = g_K;
    float dm = g_dmin[i];
    float dval; int z;
    bool cf = (create != 0) && (dm > 1000.0f);
    if (cf) {
        const float* row = X + (size_t)i * DD;
        float s = 0.f;
#pragma unroll
        for (int j = 0; j < 32; j++) {
            int d = lane + 32 * j;
            float dv = row[d] - g_nc[d];
            s = fmaf(dv, dv, s);
        }
#pragma unroll
        for (int off = 16; off > 0; off >>= 1) s += __shfl_xor_sync(0xFFFFFFFFu, s, off);
        dval = s; z = K;            // Kc == K (create implies K < KM)
    } else { dval = dm; z = g_ztmp[i]; }
    if (lane == 0) { g_z[i] = z; atomicAdd(&sh[z], 1); wv[w] = dval; }
    __syncthreads();
    if (tid == 0) {
        float s = 0.f;
        for (int q = 0; q < 8; q++) s += wv[q];
        g_objpart[blockIdx.x] = s;
    }
    if (tid < KM && sh[tid]) atomicAdd(&g_counts[tid], sh[tid]);
}

// ---------------- C2: deterministic scatter-sum partials ----------------
__global__ __launch_bounds__(128) void kC2(const float* __restrict__ X) {
    if (g_done) return;
    __shared__ float acc[KM * 128];
    __shared__ int zs[128];
    int tid = threadIdx.x;
    int dbase = blockIdx.x * 128;
    int pb = blockIdx.y * 1024;
#pragma unroll
    for (int k = 0; k < KM; k++) acc[k * 128 + tid] = 0.f;
    for (int t0 = 0; t0 < 1024; t0 += 128) {
        __syncthreads();
        zs[tid] = g_z[pb + t0 + tid];
        __syncthreads();
#pragma unroll 4
        for (int j = 0; j < 128; j++) {
            float v = X[(size_t)(pb + t0 + j) * DD + dbase + tid];
            acc[zs[j] * 128 + tid] += v;
        }
    }
    __syncthreads();
    for (int k = 0; k < KM; k++)
        g_sumpart[blockIdx.x][blockIdx.y][k][tid] = acc[k * 128 + tid];
}

// ---------------- D1: centroid update + m2 ----------------
__global__ void kD1(float* __restrict__ mu) {
    if (g_done) return;
    __shared__ float sm[256];
    int k = blockIdx.x, tid = threadIdx.x;   // 256 threads
    int cnt = g_counts[k];
#pragma unroll
    for (int j = 0; j < 4; j++) {
        int d = tid + 256 * j;
        float s = 0.f;
        for (int pb = 0; pb < 64; pb++) s += g_sumpart[d >> 7][pb][k][d & 127];
        if (cnt > 0) mu[(size_t)k * DD + d] = s / (float)cnt;
    }
    float ss = 0.f;
#pragma unroll
    for (int j = 0; j < 4; j++) {
        float m = mu[(size_t)k * DD + tid + 256 * j];
        ss = fmaf(m, m, ss);
    }
    sm[tid] = ss;
    __syncthreads();
    for (int off = 128; off > 0; off >>= 1) { if (tid < off) sm[tid] += sm[tid + off]; __syncthreads(); }
    if (tid == 0) g_m2[k] = sm[0];
}

// ---------------- D2: objective, convergence, commit scalars ----------------
__global__ void kD2() {
    if (g_done) return;
    __shared__ double sd[1024];
    int tid = threadIdx.x;
    double s = 0.0;
#pragma unroll
    for (int j = 0; j < 8; j++) s += (double)g_objpart[tid * 8 + j];
    sd[tid] = s;
    __syncthreads();
    for (int off = 512; off > 0; off >>= 1) { if (tid < off) sd[tid] += sd[tid + off]; __syncthreads(); }
    if (tid == 0) {
        int Kn = g_Knew;
        double obj = sd[0] + 1000.0 * (double)Kn;
        int it = g_it;
        bool conv = (it > 0) && (fabs(obj - g_prev) < 1e-3 * obj);
        g_prev = obj;
        g_K = Kn;
        g_it = it + 1;
        if (conv) g_done = 1;
    }
}

// ---------------- launch ----------------
extern "C" void kernel_launch(void* const* d_in, const int* in_sizes, int n_in,
                              void* d_out, int out_size) {
    const float* X = (const float*)d_in[0];
    float* mu = (float*)d_out;   // d_out (1,64,1024) doubles as the live centroid buffer

    kI1<<<NN / 8, 256>>>(X);
    kI2<<<64, 256>>>(X);
    kI3<<<1, 1024>>>(mu);

    for (int t = 0; t < 50; t++) {
        kA<<<NN / 128, 128>>>(X, mu);
        kB1<<<128, 256>>>(X);
        kB2<<<1, 1024>>>();
        kC1<<<NN / 8, 256>>>(X);
        kC2<<<dim3(8, 64), 128>>>(X);
        kD1<<<KM, 256>>>(mu);
        kD2<<<1, 1024>>>();
    }
}

// round 4
// speedup vs baseline: 1.0085x; 1.0085x over previous
#include <cuda_runtime.h>
#include <cstdint>

// ---------------- problem constants ----------------
#define NN 65536
#define DD 1024
#define KM 64
#define NSTAGE 64          // DD / 16
typedef unsigned long long ull;

// ---------------- device state ----------------
__device__ float  g_x2[NN];
__device__ float  g_dmin[NN];
__device__ int    g_ztmp[NN];
__device__ int    g_z[NN];
__device__ float  g_m2[KM];
__device__ float  g_nc[DD];
__device__ float  g_colpart[64][DD];
__device__ float  g_farpart[128][DD];
__device__ float  g_objpart[8192];
__device__ float  g_sumpart[8][64][KM][128];   // [dchunk][pblk][k][dsub] ~16.8 MB
__device__ int    g_counts[KM];
__device__ int    g_farcnt;
__device__ int    g_K, g_Knew, g_create, g_done, g_it;
__device__ double g_prev;

// ---------------- helpers ----------------
__device__ __forceinline__ ull pk2(float a, float b) {
    ull r; asm("mov.b64 %0, {%1,%2};" : "=l"(r) : "f"(a), "f"(b)); return r;
}
__device__ __forceinline__ void fma2(ull &acc, ull a, ull b) {
    asm("fma.rn.f32x2 %0, %1, %2, %0;" : "+l"(acc) : "l"(a), "l"(b));
}
__device__ __forceinline__ void un2(ull v, float &x, float &y) {
    asm("mov.b64 {%0,%1}, %2;" : "=f"(x), "=f"(y) : "l"(v));
}

// ---------------- init kernels ----------------
// I1: per-point squared norm (warp per point)
__global__ void kI1(const float* __restrict__ X) {
    int tid = threadIdx.x, w = tid >> 5, lane = tid & 31;
    int i = blockIdx.x * 8 + w;
    const float* row = X + (size_t)i * DD;
    float s = 0.f;
#pragma unroll
    for (int j = 0; j < 32; j++) { float v = row[lane + 32 * j]; s = fmaf(v, v, s); }
#pragma unroll
    for (int off = 16; off > 0; off >>= 1) s += __shfl_xor_sync(0xFFFFFFFFu, s, off);
    if (lane == 0) g_x2[i] = s;
}

// I2: column-sum partials for the initial mean
__global__ void kI2(const float* __restrict__ X) {
    int tid = threadIdx.x;
    float a0 = 0.f, a1 = 0.f, a2 = 0.f, a3 = 0.f;
    int base = blockIdx.x * 1024;
    for (int p = 0; p < 1024; p++) {
        const float* row = X + (size_t)(base + p) * DD;
        a0 += row[tid]; a1 += row[tid + 256]; a2 += row[tid + 512]; a3 += row[tid + 768];
    }
    g_colpart[blockIdx.x][tid]       = a0;
    g_colpart[blockIdx.x][tid + 256] = a1;
    g_colpart[blockIdx.x][tid + 512] = a2;
    g_colpart[blockIdx.x][tid + 768] = a3;
}

// I3: finalize mu0, zero other slots, m2, reset scalars
__global__ void kI3(float* __restrict__ mu) {
    __shared__ float sm[1024];
    int tid = threadIdx.x;
    float s = 0.f;
    for (int b = 0; b < 64; b++) s += g_colpart[b][tid];
    float m = s * (1.0f / 65536.0f);
    mu[tid] = m;
    for (int k = 1; k < KM; k++) mu[(size_t)k * DD + tid] = 0.f;
    sm[tid] = m * m;
    __syncthreads();
    for (int off = 512; off > 0; off >>= 1) { if (tid < off) sm[tid] += sm[tid + off]; __syncthreads(); }
    if (tid == 0) g_m2[0] = sm[0];
    if (tid >= 1 && tid < KM) g_m2[tid] = 0.f;
    if (tid == 0) { g_K = 1; g_done = 0; g_it = 0; g_prev = 0.0; g_create = 0; g_farcnt = 0; }
}

// ---------------- A: fused GEMM + masked min/argmin ----------------
// 512 blocks x 128 threads; block tile 128 points x 64 clusters; thread tile 8x8 via f32x2.
__global__ __launch_bounds__(128) void kA(const float* __restrict__ X, const float* __restrict__ mu) {
    if (g_done) return;
    if (blockIdx.x == 0 && threadIdx.x == 0) g_farcnt = 0;
    __shared__ float sX[16][128];
    __shared__ float sB[16][64];
    __shared__ float sx2[128];
    __shared__ float sm2[64];
    const int tid = threadIdx.x;
    const int tx = tid & 7, ty = tid >> 3;
    const int pbase = blockIdx.x * 128;
    sx2[tid] = g_x2[pbase + tid];
    if (tid < 64) sm2[tid] = g_m2[tid];
    const int K = g_K;

    ull acc[8][4];
#pragma unroll
    for (int p = 0; p < 8; p++)
#pragma unroll
        for (int q = 0; q < 4; q++) acc[p][q] = 0ull;

    for (int stage = 0; stage < NSTAGE; ++stage) {
        const int dbase = stage * 16;
        __syncthreads();
#pragma unroll
        for (int it = 0; it < 4; ++it) {
            int f = tid + it * 128;
            int p = f >> 2, q = f & 3;
            float4 v = *reinterpret_cast<const float4*>(&X[(size_t)(pbase + p) * DD + dbase + q * 4]);
            sX[q * 4 + 0][p] = v.x; sX[q * 4 + 1][p] = v.y;
            sX[q * 4 + 2][p] = v.z; sX[q * 4 + 3][p] = v.w;
        }
#pragma unroll
        for (int it = 0; it < 2; ++it) {
            int f = tid + it * 128;
            int k = f >> 2, q = f & 3;
            float4 v = *reinterpret_cast<const float4*>(&mu[(size_t)k * DD + dbase + q * 4]);
            sB[q * 4 + 0][k] = v.x; sB[q * 4 + 1][k] = v.y;
            sB[q * 4 + 2][k] = v.z; sB[q * 4 + 3][k] = v.w;
        }
        __syncthreads();
#pragma unroll
        for (int dd = 0; dd < 16; ++dd) {
            float4 a0 = *reinterpret_cast<const float4*>(&sX[dd][ty * 8]);
            float4 a1 = *reinterpret_cast<const float4*>(&sX[dd][ty * 8 + 4]);
            float4 b0 = *reinterpret_cast<const float4*>(&sB[dd][tx * 8]);
            float4 b1 = *reinterpret_cast<const float4*>(&sB[dd][tx * 8 + 4]);
            ull bp0 = pk2(b0.x, b0.y), bp1 = pk2(b0.z, b0.w);
            ull bp2 = pk2(b1.x, b1.y), bp3 = pk2(b1.z, b1.w);
            float av[8] = {a0.x, a0.y, a0.z, a0.w, a1.x, a1.y, a1.z, a1.w};
#pragma unroll
            for (int p = 0; p < 8; p++) {
                ull xx = pk2(av[p], av[p]);
                fma2(acc[p][0], xx, bp0);
                fma2(acc[p][1], xx, bp1);
                fma2(acc[p][2], xx, bp2);
                fma2(acc[p][3], xx, bp3);
            }
        }
    }

    // epilogue: dist = (x2 - 2S) + m2, mask k>=K, min + first-index argmin
#pragma unroll
    for (int p = 0; p < 8; p++) {
        int prow = ty * 8 + p;
        float x2v = sx2[prow];
        float best = 3.0e38f; int bidx = 0;
#pragma unroll
        for (int q = 0; q < 4; q++) {
            float s0, s1; un2(acc[p][q], s0, s1);
            int k0 = tx * 8 + q * 2;
            float d0 = fmaf(-2.f, s0, x2v) + sm2[k0];
            float d1 = fmaf(-2.f, s1, x2v) + sm2[k0 + 1];
            if (k0 < K && d0 < best) { best = d0; bidx = k0; }
            if (k0 + 1 < K && d1 < best) { best = d1; bidx = k0 + 1; }
        }
#pragma unroll
        for (int off = 1; off < 8; off <<= 1) {
            float ov = __shfl_xor_sync(0xFFFFFFFFu, best, off);
            int   oi = __shfl_xor_sync(0xFFFFFFFFu, bidx, off);
            if (ov < best || (ov == best && oi < bidx)) { best = ov; bidx = oi; }
        }
        if (tx == 0) { g_dmin[pbase + prow] = best; g_ztmp[pbase + prow] = bidx; }
    }
}

// ---------------- B1: masked sum of far points (partials) ----------------
__global__ void kB1(const float* __restrict__ X) {
    if (g_done) return;
    int tid = threadIdx.x;
    float a0 = 0.f, a1 = 0.f, a2 = 0.f, a3 = 0.f;
    int base = blockIdx.x * 512;
    int cnt = 0;
    for (int p = 0; p < 512; p++) {
        int i = base + p;
        if (g_dmin[i] > 1000.0f) {
            const float* row = X + (size_t)i * DD;
            a0 += row[tid]; a1 += row[tid + 256]; a2 += row[tid + 512]; a3 += row[tid + 768];
            cnt++;
        }
    }
    g_farpart[blockIdx.x][tid]       = a0;
    g_farpart[blockIdx.x][tid + 256] = a1;
    g_farpart[blockIdx.x][tid + 512] = a2;
    g_farpart[blockIdx.x][tid + 768] = a3;
    if (tid == 0) atomicAdd(&g_farcnt, cnt);
}

// ---------------- B2: new center, create flag, reset counts ----------------
__global__ void kB2() {
    if (g_done) return;
    int tid = threadIdx.x;       // 1024
    float s = 0.f;
    for (int b = 0; b < 128; b++) s += g_farpart[b][tid];
    int cnt = g_farcnt;
    g_nc[tid] = s / fmaxf((float)cnt, 1.0f);
    if (tid < KM) g_counts[tid] = 0;
    if (tid == 0) {
        int K = g_K;
        int create = (cnt > 0 && K < KM) ? 1 : 0;
        g_create = create;
        g_Knew = K + create;
    }
}

// ---------------- C1: finalize z/dvals, counts, obj partials ----------------
__global__ void kC1(const float* __restrict__ X) {
    if (g_done) return;
    __shared__ int sh[KM];
    __shared__ float wv[8];
    int tid = threadIdx.x, w = tid >> 5, lane = tid & 31;
    if (tid < KM) sh[tid] = 0;
    __syncthreads();
    int i = blockIdx.x * 8 + w;
    int create = g_create;
    int K = g_K;
    float dm = g_dmin[i];
    float dval; int z;
    bool cf = (create != 0) && (dm > 1000.0f);
    if (cf) {
        const float* row = X + (size_t)i * DD;
        float s = 0.f;
#pragma unroll
        for (int j = 0; j < 32; j++) {
            int d = lane + 32 * j;
            float dv = row[d] - g_nc[d];
            s = fmaf(dv, dv, s);
        }
#pragma unroll
        for (int off = 16; off > 0; off >>= 1) s += __shfl_xor_sync(0xFFFFFFFFu, s, off);
        dval = s; z = K;            // Kc == K (create implies K < KM)
    } else { dval = dm; z = g_ztmp[i]; }
    if (lane == 0) { g_z[i] = z; atomicAdd(&sh[z], 1); wv[w] = dval; }
    __syncthreads();
    if (tid == 0) {
        float s = 0.f;
        for (int q = 0; q < 8; q++) s += wv[q];
        g_objpart[blockIdx.x] = s;
    }
    if (tid < KM && sh[tid]) atomicAdd(&g_counts[tid], sh[tid]);
}

// ---------------- C2: deterministic scatter-sum partials ----------------
__global__ __launch_bounds__(128) void kC2(const float* __restrict__ X) {
    if (g_done) return;
    __shared__ float acc[KM * 128];
    __shared__ int zs[128];
    int tid = threadIdx.x;
    int dbase = blockIdx.x * 128;
    int pb = blockIdx.y * 1024;
#pragma unroll
    for (int k = 0; k < KM; k++) acc[k * 128 + tid] = 0.f;
    for (int t0 = 0; t0 < 1024; t0 += 128) {
        __syncthreads();
        zs[tid] = g_z[pb + t0 + tid];
        __syncthreads();
#pragma unroll 4
        for (int j = 0; j < 128; j++) {
            float v = X[(size_t)(pb + t0 + j) * DD + dbase + tid];
            acc[zs[j] * 128 + tid] += v;
        }
    }
    __syncthreads();
    for (int k = 0; k < KM; k++)
        g_sumpart[blockIdx.x][blockIdx.y][k][tid] = acc[k * 128 + tid];
}

// ---------------- D1: centroid update + m2 ----------------
__global__ void kD1(float* __restrict__ mu) {
    if (g_done) return;
    __shared__ float sm[256];
    int k = blockIdx.x, tid = threadIdx.x;   // 256 threads
    int cnt = g_counts[k];
#pragma unroll
    for (int j = 0; j < 4; j++) {
        int d = tid + 256 * j;
        float s = 0.f;
        for (int pb = 0; pb < 64; pb++) s += g_sumpart[d >> 7][pb][k][d & 127];
        if (cnt > 0) mu[(size_t)k * DD + d] = s / (float)cnt;
    }
    float ss = 0.f;
#pragma unroll
    for (int j = 0; j < 4; j++) {
        float m = mu[(size_t)k * DD + tid + 256 * j];
        ss = fmaf(m, m, ss);
    }
    sm[tid] = ss;
    __syncthreads();
    for (int off = 128; off > 0; off >>= 1) { if (tid < off) sm[tid] += sm[tid + off]; __syncthreads(); }
    if (tid == 0) g_m2[k] = sm[0];
}

// ---------------- D2: objective, convergence, commit scalars ----------------
__global__ void kD2() {
    if (g_done) return;
    __shared__ double sd[1024];
    int tid = threadIdx.x;
    double s = 0.0;
#pragma unroll
    for (int j = 0; j < 8; j++) s += (double)g_objpart[tid * 8 + j];
    sd[tid] = s;
    __syncthreads();
    for (int off = 512; off > 0; off >>= 1) { if (tid < off) sd[tid] += sd[tid + off]; __syncthreads(); }
    if (tid == 0) {
        int Kn = g_Knew;
        double obj = sd[0] + 1000.0 * (double)Kn;
        int it = g_it;
        bool conv = (it > 0) && (fabs(obj - g_prev) < 1e-3 * obj);
        g_prev = obj;
        g_K = Kn;
        g_it = it + 1;
        if (conv) g_done = 1;
    }
}

// ---------------- launch ----------------
extern "C" void kernel_launch(void* const* d_in, const int* in_sizes, int n_in,
                              void* d_out, int out_size) {
    const float* X = (const float*)d_in[0];
    float* mu = (float*)d_out;   // d_out (1,64,1024) doubles as the live centroid buffer

    kI1<<<NN / 8, 256>>>(X);
    kI2<<<64, 256>>>(X);
    kI3<<<1, 1024>>>(mu);

    for (int t = 0; t < 50; t++) {
        kA<<<NN / 128, 128>>>(X, mu);
        kB1<<<128, 256>>>(X);
        kB2<<<1, 1024>>>();
        kC1<<<NN / 8, 256>>>(X);
        kC2<<<dim3(8, 64), 128>>>(X);
        kD1<<<KM, 256>>>(mu);
        kD2<<<1, 1024>>>();
    }
}